// round 14
// baseline (speedup 1.0000x reference)
#include <cuda_runtime.h>
#include <cuda_fp16.h>
#include <math.h>
#include <stdint.h>

#define BB 4
#define SS 2048
#define DIMX 1024
#define DQK 128
#define DV 1024
#define MROWS (BB * SS)   // 8192

// ---------------------------------------------------------------------------
// scratch (__device__ globals; no dynamic allocation)
// ---------------------------------------------------------------------------
__device__ __align__(256) __half g_x[(size_t)MROWS * DIMX];
__device__ __align__(256) __half g_wqk[DIMX * DQK];                // [k][n]
__device__ __align__(256) __half g_wv[(size_t)DIMX * DV];          // [k][n]
__device__ __align__(256) __half g_q[(size_t)MROWS * DQK];
__device__ __align__(256) __half g_k[(size_t)MROWS * DQK];
__device__ __align__(256) __half g_v[(size_t)MROWS * DV];          // [row][dv]
__device__ __align__(256) __half g_attn[(size_t)BB * SS * SS];
__device__ float g_bias[SS];

// ---------------------------------------------------------------------------
// helpers
// ---------------------------------------------------------------------------
__device__ __forceinline__ uint32_t smem_to_u32(const void* p) {
    uint32_t a;
    asm("{ .reg .u64 t; cvta.to.shared.u64 t, %1; cvt.u32.u64 %0, t; }"
        : "=r"(a) : "l"(p));
    return a;
}
__device__ __forceinline__ uint32_t sw128(uint32_t o) {
    return o ^ ((o >> 3) & 0x70);
}
__device__ __forceinline__ void cp16(uint32_t dst, const void* src) {
    asm volatile("cp.async.cg.shared.global [%0], [%1], 16;" :: "r"(dst), "l"(src));
}
__device__ __forceinline__ void ldmx4(uint32_t* r, uint32_t a) {
    asm volatile("ldmatrix.sync.aligned.m8n8.x4.shared.b16 {%0,%1,%2,%3}, [%4];"
        : "=r"(r[0]), "=r"(r[1]), "=r"(r[2]), "=r"(r[3]) : "r"(a));
}
__device__ __forceinline__ void ldmx4t(uint32_t* r, uint32_t a) {
    asm volatile("ldmatrix.sync.aligned.m8n8.x4.trans.shared.b16 {%0,%1,%2,%3}, [%4];"
        : "=r"(r[0]), "=r"(r[1]), "=r"(r[2]), "=r"(r[3]) : "r"(a));
}
__device__ __forceinline__ void mma16816(float* d, const uint32_t* a, const uint32_t* b) {
    asm volatile(
        "mma.sync.aligned.m16n8k16.row.col.f32.f16.f16.f32 "
        "{%0,%1,%2,%3}, {%4,%5,%6,%7}, {%8,%9}, {%0,%1,%2,%3};"
        : "+f"(d[0]), "+f"(d[1]), "+f"(d[2]), "+f"(d[3])
        : "r"(a[0]), "r"(a[1]), "r"(a[2]), "r"(a[3]), "r"(b[0]), "r"(b[1]));
}

__device__ __forceinline__ float silu_f(float x) { return x / (1.0f + expf(-x)); }
__device__ __forceinline__ float lapl_f(float x) {
    return 0.5f * (1.0f + erff((x - 0.70710678118654746f) * 0.79788456080286541f));
}
__device__ __forceinline__ uint32_t pack_h2(float a, float b) {
    __half2 h2 = __floats2half2_rn(a, b);
    return *reinterpret_cast<uint32_t*>(&h2);
}

// ---------------------------------------------------------------------------
// tile geometry: CTA 64x128, chunk K=64, 256 threads, 8 warps (2m x 4n),
// warp tile 32x32. A tile: 64 rows x 128B SW128. B(nmajor): 128 rows x 128B
// SW128. B(kmajor/trans): 64 rows x 272B. 2-stage smem pipeline.
// DBUF: optional register double-buffering of fragments (used by tc_out).
// ---------------------------------------------------------------------------
#define ATILE 8192
template <int ROWS>
__device__ __forceinline__ void ld_tile_nmajor(uint32_t dst, const __half* src,
                                               int ld, int tid) {
#pragma unroll
    for (int s = 0; s < ROWS / 32; s++) {
        int idx = tid + s * 256;
        int row = idx >> 3, seg = idx & 7;
        uint32_t off = (uint32_t)(row * 128 + seg * 16);
        cp16(dst + sw128(off), src + (size_t)row * ld + seg * 8);
    }
}
__device__ __forceinline__ void ld_tile_kmajor(uint32_t dst, const __half* src,
                                               int ld, int tid) {
#pragma unroll
    for (int s = 0; s < 4; s++) {
        int idx = tid + s * 256;
        int row = idx >> 4, seg = idx & 15;
        cp16(dst + (uint32_t)(row * 272 + seg * 16), src + (size_t)row * ld + seg * 8);
    }
}

template <bool BTRANS>
__device__ __forceinline__ void ld_frags(uint32_t A_s, uint32_t B_s,
                                         const uint32_t* a_raw, const uint32_t* b_raw,
                                         int ks, uint32_t ah[2][4], uint32_t bh[2][4]) {
#pragma unroll
    for (int i = 0; i < 2; i++)
        ldmx4(ah[i], A_s + sw128(a_raw[i] + ks * 32));
    if (!BTRANS) {
#pragma unroll
        for (int g = 0; g < 2; g++)
            ldmx4(bh[g], B_s + sw128(b_raw[g] + ks * 32));
    } else {
#pragma unroll
        for (int g = 0; g < 2; g++)
            ldmx4t(bh[g], B_s + b_raw[g] + ks * 4352);
    }
}

template <bool BTRANS, bool DBUF>
__device__ __forceinline__ void compute_stage(uint32_t st, float acc[2][4][4], int tid) {
    const int lane = tid & 31, wid = tid >> 5, wm = wid & 1, wn = wid >> 1;
    uint32_t a_raw[2];
#pragma unroll
    for (int i = 0; i < 2; i++) {
        uint32_t row = wm * 32 + i * 16 + (lane & 15);
        a_raw[i] = row * 128 + ((lane >> 4) << 4);
    }
    uint32_t b_raw[2];
    const uint32_t m = lane >> 3;
    if (!BTRANS) {
#pragma unroll
        for (int g = 0; g < 2; g++) {
            uint32_t row = wn * 32 + g * 16 + ((m >> 1) << 3) + (lane & 7);
            b_raw[g] = row * 128 + ((m & 1) << 4);
        }
    } else {
#pragma unroll
        for (int g = 0; g < 2; g++) {
            uint32_t krow = ((m & 1) << 3) + (lane & 7);
            uint32_t ncol = wn * 32 + g * 16 + ((m >> 1) << 3);
            b_raw[g] = krow * 272 + ncol * 2;
        }
    }
    const uint32_t A_s = st, B_s = st + ATILE;

    if (DBUF) {
        uint32_t ah[2][2][4], bh[2][2][4];
        ld_frags<BTRANS>(A_s, B_s, a_raw, b_raw, 0, ah[0], bh[0]);
#pragma unroll
        for (int ks = 0; ks < 4; ks++) {
            const int cur = ks & 1, nxt = cur ^ 1;
            if (ks < 3)
                ld_frags<BTRANS>(A_s, B_s, a_raw, b_raw, ks + 1, ah[nxt], bh[nxt]);
#pragma unroll
            for (int i = 0; i < 2; i++)
#pragma unroll
                for (int j = 0; j < 4; j++)
                    mma16816(acc[i][j], ah[cur][i], &bh[cur][j >> 1][(j & 1) * 2]);
        }
    } else {
#pragma unroll
        for (int ks = 0; ks < 4; ks++) {
            uint32_t ah[2][4], bh[2][4];
            ld_frags<BTRANS>(A_s, B_s, a_raw, b_raw, ks, ah, bh);
#pragma unroll
            for (int i = 0; i < 2; i++)
#pragma unroll
                for (int j = 0; j < 4; j++)
                    mma16816(acc[i][j], ah[i], &bh[j >> 1][(j & 1) * 2]);
        }
    }
}

// 2-stage pipeline; single __syncthreads per chunk
template <bool BTRANS, bool DBUF>
__device__ __forceinline__ void gemm_run(uint32_t sb, float acc[2][4][4],
    const __half* A, int lda, const __half* B, int ldb, int nk)
{
    constexpr uint32_t BTILE = BTRANS ? 17408u : 16384u;
    constexpr uint32_t STAGE = ATILE + BTILE;
    const int tid = threadIdx.x;
#pragma unroll
    for (int i = 0; i < 2; i++)
#pragma unroll
        for (int j = 0; j < 4; j++)
#pragma unroll
            for (int r = 0; r < 4; r++) acc[i][j][r] = 0.0f;

#define LOAD_CHUNK(stg, c) do {                                                      \
        uint32_t base_ = sb + (stg) * STAGE;                                         \
        ld_tile_nmajor<64>(base_, A + (size_t)(c) * 64, lda, tid);                   \
        if (BTRANS) ld_tile_kmajor(base_ + ATILE, B + (size_t)(c) * 64 * ldb, ldb, tid); \
        else        ld_tile_nmajor<128>(base_ + ATILE, B + (size_t)(c) * 64, ldb, tid); \
    } while (0)

    LOAD_CHUNK(0, 0);
    asm volatile("cp.async.commit_group;");
    for (int i = 0; i < nk; i++) {
        int st = i & 1;
        asm volatile("cp.async.wait_group 0;");
        __syncthreads();
        if (i + 1 < nk) {
            LOAD_CHUNK(st ^ 1, i + 1);
            asm volatile("cp.async.commit_group;");
        }
        compute_stage<BTRANS, DBUF>(sb + st * STAGE, acc, tid);
    }
#undef LOAD_CHUNK
}

#define SMEM_PROJ (2 * (8192 + 17408))   // 51200
#define SMEM_SIM  (2 * (8192 + 16384))   // 49152
#define SMEM_OUT  (2 * (8192 + 17408))   // 51200

// ---------------------------------------------------------------------------
// prep: converts x, wqk, wv (4 independent vec4 per thread) + bias table
// ---------------------------------------------------------------------------
#define NX ((size_t)MROWS * DIMX)                 // 8388608
#define NWQ ((size_t)DIMX * DQK)                  // 131072
#define NWV ((size_t)DIMX * DV)                   // 1048576
#define CVT_TOTAL ((NX + NWQ + NWV) / 4)          // 2392064 vec4 elements
#define PREP_THREADS ((CVT_TOTAL + 3) / 4)        // 598016
#define PREP_BLOCKS ((PREP_THREADS + 255) / 256)  // 2336

__device__ __forceinline__ void cvt_one(const float* __restrict__ x,
                                        const float* __restrict__ wqk,
                                        const float* __restrict__ wv, size_t vi) {
    const float* src;
    __half* dst;
    size_t off;
    if (vi < NX / 4) {
        src = x; dst = g_x; off = vi * 4;
    } else if (vi < (NX + NWQ) / 4) {
        src = wqk; dst = g_wqk; off = vi * 4 - NX;
    } else {
        src = wv; dst = g_wv; off = vi * 4 - NX - NWQ;
    }
    float4 f = *reinterpret_cast<const float4*>(src + off);
    uint2 o;
    o.x = pack_h2(f.x, f.y);
    o.y = pack_h2(f.z, f.w);
    *reinterpret_cast<uint2*>(dst + off) = o;
}

__global__ void prep_kernel(const float* __restrict__ x, const float* __restrict__ wqk,
                            const float* __restrict__ wv, const float* __restrict__ table) {
    size_t t = (size_t)blockIdx.x * blockDim.x + threadIdx.x;
    if (t < SS) {
        int d = (int)t;
        int bkt;
        if (d < 16) {
            bkt = d;
        } else {
            float tt = logf((float)d * 0.0625f) * (16.0f / 2.0794415416798357f);
            int v = 16 + (int)tt;
            bkt = v < 31 ? v : 31;
        }
        g_bias[d] = table[bkt] * 11.313708498984761f;
    }
#pragma unroll
    for (int s = 0; s < 4; s++) {
        size_t vi = t + (size_t)s * PREP_THREADS;
        if (vi < CVT_TOTAL) cvt_one(x, wqk, wv, vi);
    }
}

// ---------------------------------------------------------------------------
// GEMM kernels (CTA tile 64x128)
// ---------------------------------------------------------------------------
__global__ __launch_bounds__(256, 3) void tc_proj_qk(
    const float* __restrict__ bqk, const float* __restrict__ gamma,
    const float* __restrict__ beta)
{
    extern __shared__ __align__(1024) char smem[];
    uint32_t sb = smem_to_u32(smem);
    const int tid = threadIdx.x, lane = tid & 31, wid = tid >> 5;
    const int wm = wid & 1, wn = wid >> 1, t4 = lane >> 2, tm4 = lane & 3;
    float acc[2][4][4];
    const int mt = blockIdx.x;
    gemm_run<true, false>(sb, acc, g_x + (size_t)mt * 64 * DIMX, DIMX,
                          g_wqk, DQK, DIMX / 64);
#pragma unroll
    for (int i = 0; i < 2; i++)
#pragma unroll
        for (int rr = 0; rr < 2; rr++) {
            int row = mt * 64 + wm * 32 + i * 16 + t4 + 8 * rr;
#pragma unroll
            for (int j = 0; j < 4; j++) {
                int c = wn * 32 + j * 8 + 2 * tm4;
                float f0 = silu_f(acc[i][j][2 * rr + 0] + bqk[c]);
                float f1 = silu_f(acc[i][j][2 * rr + 1] + bqk[c + 1]);
                float q0 = f0 * gamma[c] + beta[c];
                float q1 = f1 * gamma[c + 1] + beta[c + 1];
                float k0 = f0 * gamma[DQK + c] + beta[DQK + c];
                float k1 = f1 * gamma[DQK + c + 1] + beta[DQK + c + 1];
                size_t o = (size_t)row * DQK + c;
                *reinterpret_cast<uint32_t*>(g_q + o) = pack_h2(q0, q1);
                *reinterpret_cast<uint32_t*>(g_k + o) = pack_h2(k0, k1);
            }
        }
}

__global__ __launch_bounds__(256, 3) void tc_proj_v(const float* __restrict__ bv)
{
    extern __shared__ __align__(1024) char smem[];
    uint32_t sb = smem_to_u32(smem);
    const int tid = threadIdx.x, lane = tid & 31, wid = tid >> 5;
    const int wm = wid & 1, wn = wid >> 1, t4 = lane >> 2, tm4 = lane & 3;
    float acc[2][4][4];
    const int nt = blockIdx.x & 7, mt = blockIdx.x >> 3;
    gemm_run<true, false>(sb, acc, g_x + (size_t)mt * 64 * DIMX, DIMX,
                          g_wv + nt * 128, DV, DIMX / 64);
#pragma unroll
    for (int i = 0; i < 2; i++)
#pragma unroll
        for (int rr = 0; rr < 2; rr++) {
            int row = mt * 64 + wm * 32 + i * 16 + t4 + 8 * rr;
#pragma unroll
            for (int j = 0; j < 4; j++) {
                int c = nt * 128 + wn * 32 + j * 8 + 2 * tm4;
                float f0 = silu_f(acc[i][j][2 * rr + 0] + bv[c]);
                float f1 = silu_f(acc[i][j][2 * rr + 1] + bv[c + 1]);
                *reinterpret_cast<uint32_t*>(g_v + (size_t)row * DV + c) = pack_h2(f0, f1);
            }
        }
}

// causal tiles: rows it*64..+64, cols jt*128..+128, jt <= it/2. 272 tiles/batch.
__global__ __launch_bounds__(256, 3) void tc_sim()
{
    extern __shared__ __align__(1024) char smem[];
    uint32_t sb = smem_to_u32(smem);
    int t = blockIdx.x;
    const int b = blockIdx.y;
    int it = 0, c0 = 0;
    while (c0 + (it >> 1) + 1 <= t) { c0 += (it >> 1) + 1; it++; }
    const int jt = t - c0;
    const size_t qoff = ((size_t)b * SS + it * 64) * DQK;
    const size_t koff = ((size_t)b * SS + jt * 128) * DQK;
    float acc[2][4][4];
    gemm_run<false, false>(sb, acc, g_q + qoff, DQK, g_k + koff, DQK, DQK / 64);
    const int tid = threadIdx.x, lane = tid & 31, wid = tid >> 5;
    const int wm = wid & 1, wn = wid >> 1, t4 = lane >> 2, tm4 = lane & 3;
    const float invS = 1.0f / (float)SS;
    const size_t bb = (size_t)b * SS * SS;
#pragma unroll
    for (int i = 0; i < 2; i++)
#pragma unroll
        for (int rr = 0; rr < 2; rr++) {
            int gi = it * 64 + wm * 32 + i * 16 + t4 + 8 * rr;
#pragma unroll
            for (int j = 0; j < 4; j++) {
                int gj = jt * 128 + wn * 32 + j * 8 + 2 * tm4;
                float v0 = 0.0f, v1 = 0.0f;
                if (gj <= gi)
                    v0 = lapl_f(acc[i][j][2 * rr + 0] * invS + g_bias[gi - gj]);
                if (gj + 1 <= gi)
                    v1 = lapl_f(acc[i][j][2 * rr + 1] * invS + g_bias[gi - gj - 1]);
                size_t o = bb + (size_t)gi * SS + gj;
                *reinterpret_cast<uint32_t*>(g_attn + o) = pack_h2(v0, v1);
            }
        }
}

__global__ __launch_bounds__(256, 2) void tc_out(float* __restrict__ out)
{
    extern __shared__ __align__(1024) char smem[];
    uint32_t sb = smem_to_u32(smem);
    const int nt = blockIdx.x;
    const int it = 31 - blockIdx.y;   // heaviest first
    const int b = blockIdx.z;
    const int nk = it + 1;            // K extent = (it+1)*64
    const size_t aoff = ((size_t)b * SS + it * 64) * SS;
    float acc[2][4][4];
    gemm_run<true, true>(sb, acc, g_attn + aoff, SS,
                         g_v + (size_t)b * SS * DV + nt * 128, DV, nk);
    const int tid = threadIdx.x, lane = tid & 31, wid = tid >> 5;
    const int wm = wid & 1, wn = wid >> 1, t4 = lane >> 2, tm4 = lane & 3;
#pragma unroll
    for (int i = 0; i < 2; i++)
#pragma unroll
        for (int rr = 0; rr < 2; rr++) {
            int row = it * 64 + wm * 32 + i * 16 + t4 + 8 * rr;
#pragma unroll
            for (int j = 0; j < 4; j++) {
                int c = nt * 128 + wn * 32 + j * 8 + 2 * tm4;
                float2 v;
                v.x = acc[i][j][2 * rr + 0];
                v.y = acc[i][j][2 * rr + 1];
                *reinterpret_cast<float2*>(out + ((size_t)b * SS + row) * DV + c) = v;
            }
        }
}

// ---------------------------------------------------------------------------
// launch: fork-join streams — {proj_qk -> sim} overlaps proj_v
// ---------------------------------------------------------------------------
extern "C" void kernel_launch(void* const* d_in, const int* in_sizes, int n_in,
                              void* d_out, int out_size)
{
    const float* x     = (const float*)d_in[0];
    const float* wqk   = (const float*)d_in[1];
    const float* bqk   = (const float*)d_in[2];
    const float* gamma = (const float*)d_in[3];
    const float* beta  = (const float*)d_in[4];
    const float* wv    = (const float*)d_in[5];
    const float* bv    = (const float*)d_in[6];
    const float* rel   = (const float*)d_in[7];
    float* out = (float*)d_out;

    cudaFuncSetAttribute(tc_proj_qk, cudaFuncAttributeMaxDynamicSharedMemorySize, SMEM_PROJ);
    cudaFuncSetAttribute(tc_proj_v,  cudaFuncAttributeMaxDynamicSharedMemorySize, SMEM_PROJ);
    cudaFuncSetAttribute(tc_sim,     cudaFuncAttributeMaxDynamicSharedMemorySize, SMEM_SIM);
    cudaFuncSetAttribute(tc_out,     cudaFuncAttributeMaxDynamicSharedMemorySize, SMEM_OUT);

    cudaStream_t s2;
    cudaEvent_t e1, e2;
    bool forked = (cudaStreamCreateWithFlags(&s2, cudaStreamNonBlocking) == cudaSuccess) &&
                  (cudaEventCreateWithFlags(&e1, cudaEventDisableTiming) == cudaSuccess) &&
                  (cudaEventCreateWithFlags(&e2, cudaEventDisableTiming) == cudaSuccess);

    prep_kernel<<<PREP_BLOCKS, 256>>>(x, wqk, wv, rel);

    if (forked) {
        cudaEventRecord(e1, 0);
        cudaStreamWaitEvent(s2, e1, 0);
        tc_proj_v<<<1024, 256, SMEM_PROJ, s2>>>(bv);
        cudaEventRecord(e2, s2);
        tc_proj_qk<<<128, 256, SMEM_PROJ>>>(bqk, gamma, beta);
        tc_sim<<<dim3(272, BB), 256, SMEM_SIM>>>();
        cudaStreamWaitEvent(0, e2, 0);
    } else {
        tc_proj_v<<<1024, 256, SMEM_PROJ>>>(bv);
        tc_proj_qk<<<128, 256, SMEM_PROJ>>>(bqk, gamma, beta);
        tc_sim<<<dim3(272, BB), 256, SMEM_SIM>>>();
    }
    tc_out<<<dim3(DV / 128, SS / 64, BB), 256, SMEM_OUT>>>(out);
}

// round 15
// speedup vs baseline: 1.0369x; 1.0369x over previous
#include <cuda_runtime.h>
#include <cuda_fp16.h>
#include <math.h>
#include <stdint.h>

#define BB 4
#define SS 2048
#define DIMX 1024
#define DQK 128
#define DV 1024
#define MROWS (BB * SS)   // 8192

// ---------------------------------------------------------------------------
// scratch (__device__ globals; no dynamic allocation)
// ---------------------------------------------------------------------------
__device__ __align__(256) __half g_x[(size_t)MROWS * DIMX];
__device__ __align__(256) __half g_wqk[DIMX * DQK];                // [k][n]
__device__ __align__(256) __half g_wv[(size_t)DIMX * DV];          // [k][n]
__device__ __align__(256) __half g_q[(size_t)MROWS * DQK];
__device__ __align__(256) __half g_k[(size_t)MROWS * DQK];
__device__ __align__(256) __half g_v[(size_t)MROWS * DV];          // [row][dv]
__device__ __align__(256) __half g_attn[(size_t)BB * SS * SS];
__device__ float g_bias[SS];

// ---------------------------------------------------------------------------
// helpers
// ---------------------------------------------------------------------------
__device__ __forceinline__ uint32_t smem_to_u32(const void* p) {
    uint32_t a;
    asm("{ .reg .u64 t; cvta.to.shared.u64 t, %1; cvt.u32.u64 %0, t; }"
        : "=r"(a) : "l"(p));
    return a;
}
__device__ __forceinline__ uint32_t sw128(uint32_t o) {
    return o ^ ((o >> 3) & 0x70);
}
__device__ __forceinline__ void cp16(uint32_t dst, const void* src) {
    asm volatile("cp.async.cg.shared.global [%0], [%1], 16;" :: "r"(dst), "l"(src));
}
__device__ __forceinline__ void ldmx4(uint32_t* r, uint32_t a) {
    asm volatile("ldmatrix.sync.aligned.m8n8.x4.shared.b16 {%0,%1,%2,%3}, [%4];"
        : "=r"(r[0]), "=r"(r[1]), "=r"(r[2]), "=r"(r[3]) : "r"(a));
}
__device__ __forceinline__ void ldmx4t(uint32_t* r, uint32_t a) {
    asm volatile("ldmatrix.sync.aligned.m8n8.x4.trans.shared.b16 {%0,%1,%2,%3}, [%4];"
        : "=r"(r[0]), "=r"(r[1]), "=r"(r[2]), "=r"(r[3]) : "r"(a));
}
__device__ __forceinline__ void mma16816(float* d, const uint32_t* a, const uint32_t* b) {
    asm volatile(
        "mma.sync.aligned.m16n8k16.row.col.f32.f16.f16.f32 "
        "{%0,%1,%2,%3}, {%4,%5,%6,%7}, {%8,%9}, {%0,%1,%2,%3};"
        : "+f"(d[0]), "+f"(d[1]), "+f"(d[2]), "+f"(d[3])
        : "r"(a[0]), "r"(a[1]), "r"(a[2]), "r"(a[3]), "r"(b[0]), "r"(b[1]));
}

__device__ __forceinline__ float silu_f(float x) { return x / (1.0f + expf(-x)); }
__device__ __forceinline__ float lapl_f(float x) {
    return 0.5f * (1.0f + erff((x - 0.70710678118654746f) * 0.79788456080286541f));
}
__device__ __forceinline__ uint32_t pack_h2(float a, float b) {
    __half2 h2 = __floats2half2_rn(a, b);
    return *reinterpret_cast<uint32_t*>(&h2);
}

// ---------------------------------------------------------------------------
// tile geometry: CTA 64x128, chunk K=64, 256 threads, 8 warps (2m x 4n),
// warp tile 32x32. A tile: 64 rows x 128B SW128. B(nmajor): 128 rows x 128B
// SW128. B(kmajor/trans): 64 rows x 272B. 2-stage smem pipeline.
// DBUF: register double-buffered fragments (tc_out only).
// ---------------------------------------------------------------------------
#define ATILE 8192
template <int ROWS>
__device__ __forceinline__ void ld_tile_nmajor(uint32_t dst, const __half* src,
                                               int ld, int tid) {
#pragma unroll
    for (int s = 0; s < ROWS / 32; s++) {
        int idx = tid + s * 256;
        int row = idx >> 3, seg = idx & 7;
        uint32_t off = (uint32_t)(row * 128 + seg * 16);
        cp16(dst + sw128(off), src + (size_t)row * ld + seg * 8);
    }
}
__device__ __forceinline__ void ld_tile_kmajor(uint32_t dst, const __half* src,
                                               int ld, int tid) {
#pragma unroll
    for (int s = 0; s < 4; s++) {
        int idx = tid + s * 256;
        int row = idx >> 4, seg = idx & 15;
        cp16(dst + (uint32_t)(row * 272 + seg * 16), src + (size_t)row * ld + seg * 8);
    }
}

template <bool BTRANS>
__device__ __forceinline__ void ld_frags(uint32_t A_s, uint32_t B_s,
                                         const uint32_t* a_raw, const uint32_t* b_raw,
                                         int ks, uint32_t ah[2][4], uint32_t bh[2][4]) {
#pragma unroll
    for (int i = 0; i < 2; i++)
        ldmx4(ah[i], A_s + sw128(a_raw[i] + ks * 32));
    if (!BTRANS) {
#pragma unroll
        for (int g = 0; g < 2; g++)
            ldmx4(bh[g], B_s + sw128(b_raw[g] + ks * 32));
    } else {
#pragma unroll
        for (int g = 0; g < 2; g++)
            ldmx4t(bh[g], B_s + b_raw[g] + ks * 4352);
    }
}

template <bool BTRANS, bool DBUF>
__device__ __forceinline__ void compute_stage(uint32_t st, float acc[2][4][4], int tid) {
    const int lane = tid & 31, wid = tid >> 5, wm = wid & 1, wn = wid >> 1;
    uint32_t a_raw[2];
#pragma unroll
    for (int i = 0; i < 2; i++) {
        uint32_t row = wm * 32 + i * 16 + (lane & 15);
        a_raw[i] = row * 128 + ((lane >> 4) << 4);
    }
    uint32_t b_raw[2];
    const uint32_t m = lane >> 3;
    if (!BTRANS) {
#pragma unroll
        for (int g = 0; g < 2; g++) {
            uint32_t row = wn * 32 + g * 16 + ((m >> 1) << 3) + (lane & 7);
            b_raw[g] = row * 128 + ((m & 1) << 4);
        }
    } else {
#pragma unroll
        for (int g = 0; g < 2; g++) {
            uint32_t krow = ((m & 1) << 3) + (lane & 7);
            uint32_t ncol = wn * 32 + g * 16 + ((m >> 1) << 3);
            b_raw[g] = krow * 272 + ncol * 2;
        }
    }
    const uint32_t A_s = st, B_s = st + ATILE;

    if (DBUF) {
        uint32_t ah[2][2][4], bh[2][2][4];
        ld_frags<BTRANS>(A_s, B_s, a_raw, b_raw, 0, ah[0], bh[0]);
#pragma unroll
        for (int ks = 0; ks < 4; ks++) {
            const int cur = ks & 1, nxt = cur ^ 1;
            if (ks < 3)
                ld_frags<BTRANS>(A_s, B_s, a_raw, b_raw, ks + 1, ah[nxt], bh[nxt]);
#pragma unroll
            for (int i = 0; i < 2; i++)
#pragma unroll
                for (int j = 0; j < 4; j++)
                    mma16816(acc[i][j], ah[cur][i], &bh[cur][j >> 1][(j & 1) * 2]);
        }
    } else {
#pragma unroll
        for (int ks = 0; ks < 4; ks++) {
            uint32_t ah[2][4], bh[2][4];
            ld_frags<BTRANS>(A_s, B_s, a_raw, b_raw, ks, ah, bh);
#pragma unroll
            for (int i = 0; i < 2; i++)
#pragma unroll
                for (int j = 0; j < 4; j++)
                    mma16816(acc[i][j], ah[i], &bh[j >> 1][(j & 1) * 2]);
        }
    }
}

// 2-stage pipeline; single __syncthreads per chunk
template <bool BTRANS, bool DBUF>
__device__ __forceinline__ void gemm_run(uint32_t sb, float acc[2][4][4],
    const __half* A, int lda, const __half* B, int ldb, int nk)
{
    constexpr uint32_t BTILE = BTRANS ? 17408u : 16384u;
    constexpr uint32_t STAGE = ATILE + BTILE;
    const int tid = threadIdx.x;
#pragma unroll
    for (int i = 0; i < 2; i++)
#pragma unroll
        for (int j = 0; j < 4; j++)
#pragma unroll
            for (int r = 0; r < 4; r++) acc[i][j][r] = 0.0f;

#define LOAD_CHUNK(stg, c) do {                                                      \
        uint32_t base_ = sb + (stg) * STAGE;                                         \
        ld_tile_nmajor<64>(base_, A + (size_t)(c) * 64, lda, tid);                   \
        if (BTRANS) ld_tile_kmajor(base_ + ATILE, B + (size_t)(c) * 64 * ldb, ldb, tid); \
        else        ld_tile_nmajor<128>(base_ + ATILE, B + (size_t)(c) * 64, ldb, tid); \
    } while (0)

    LOAD_CHUNK(0, 0);
    asm volatile("cp.async.commit_group;");
    for (int i = 0; i < nk; i++) {
        int st = i & 1;
        asm volatile("cp.async.wait_group 0;");
        __syncthreads();
        if (i + 1 < nk) {
            LOAD_CHUNK(st ^ 1, i + 1);
            asm volatile("cp.async.commit_group;");
        }
        compute_stage<BTRANS, DBUF>(sb + st * STAGE, acc, tid);
    }
#undef LOAD_CHUNK
}

#define SMEM_PROJ (2 * (8192 + 17408))          // 51200
#define SMEM_SIM  (2 * (8192 + 16384) + 1024)   // 50176 (+256-float bias window)
#define SMEM_OUT  (2 * (8192 + 17408))          // 51200

// ---------------------------------------------------------------------------
// prep: converts x, wqk, wv (4 independent vec4 per thread) + bias table
// ---------------------------------------------------------------------------
#define NX ((size_t)MROWS * DIMX)                 // 8388608
#define NWQ ((size_t)DIMX * DQK)                  // 131072
#define NWV ((size_t)DIMX * DV)                   // 1048576
#define CVT_TOTAL ((NX + NWQ + NWV) / 4)          // 2392064 vec4 elements
#define PREP_THREADS ((CVT_TOTAL + 3) / 4)        // 598016
#define PREP_BLOCKS ((PREP_THREADS + 255) / 256)  // 2336

__device__ __forceinline__ void cvt_one(const float* __restrict__ x,
                                        const float* __restrict__ wqk,
                                        const float* __restrict__ wv, size_t vi) {
    const float* src;
    __half* dst;
    size_t off;
    if (vi < NX / 4) {
        src = x; dst = g_x; off = vi * 4;
    } else if (vi < (NX + NWQ) / 4) {
        src = wqk; dst = g_wqk; off = vi * 4 - NX;
    } else {
        src = wv; dst = g_wv; off = vi * 4 - NX - NWQ;
    }
    float4 f = *reinterpret_cast<const float4*>(src + off);
    uint2 o;
    o.x = pack_h2(f.x, f.y);
    o.y = pack_h2(f.z, f.w);
    *reinterpret_cast<uint2*>(dst + off) = o;
}

__global__ void prep_kernel(const float* __restrict__ x, const float* __restrict__ wqk,
                            const float* __restrict__ wv, const float* __restrict__ table) {
    size_t t = (size_t)blockIdx.x * blockDim.x + threadIdx.x;
    if (t < SS) {
        int d = (int)t;
        int bkt;
        if (d < 16) {
            bkt = d;
        } else {
            float tt = logf((float)d * 0.0625f) * (16.0f / 2.0794415416798357f);
            int v = 16 + (int)tt;
            bkt = v < 31 ? v : 31;
        }
        g_bias[d] = table[bkt] * 11.313708498984761f;
    }
#pragma unroll
    for (int s = 0; s < 4; s++) {
        size_t vi = t + (size_t)s * PREP_THREADS;
        if (vi < CVT_TOTAL) cvt_one(x, wqk, wv, vi);
    }
}

// ---------------------------------------------------------------------------
// GEMM kernels (CTA tile 64x128); merged projections
// ---------------------------------------------------------------------------
__global__ __launch_bounds__(256, 3) void tc_proj(
    const float* __restrict__ bqk, const float* __restrict__ gamma,
    const float* __restrict__ beta, const float* __restrict__ bv)
{
    extern __shared__ __align__(1024) char smem[];
    uint32_t sb = smem_to_u32(smem);
    const int tid = threadIdx.x, lane = tid & 31, wid = tid >> 5;
    const int wm = wid & 1, wn = wid >> 1, t4 = lane >> 2, tm4 = lane & 3;
    float acc[2][4][4];

    if (blockIdx.x < 128) {
        const int mt = blockIdx.x;
        gemm_run<true, false>(sb, acc, g_x + (size_t)mt * 64 * DIMX, DIMX,
                              g_wqk, DQK, DIMX / 64);
#pragma unroll
        for (int i = 0; i < 2; i++)
#pragma unroll
            for (int rr = 0; rr < 2; rr++) {
                int row = mt * 64 + wm * 32 + i * 16 + t4 + 8 * rr;
#pragma unroll
                for (int j = 0; j < 4; j++) {
                    int c = wn * 32 + j * 8 + 2 * tm4;
                    float f0 = silu_f(acc[i][j][2 * rr + 0] + bqk[c]);
                    float f1 = silu_f(acc[i][j][2 * rr + 1] + bqk[c + 1]);
                    float q0 = f0 * gamma[c] + beta[c];
                    float q1 = f1 * gamma[c + 1] + beta[c + 1];
                    float k0 = f0 * gamma[DQK + c] + beta[DQK + c];
                    float k1 = f1 * gamma[DQK + c + 1] + beta[DQK + c + 1];
                    size_t o = (size_t)row * DQK + c;
                    *reinterpret_cast<uint32_t*>(g_q + o) = pack_h2(q0, q1);
                    *reinterpret_cast<uint32_t*>(g_k + o) = pack_h2(k0, k1);
                }
            }
    } else {
        const int id = blockIdx.x - 128;
        const int nt = id & 7, mt = id >> 3;
        gemm_run<true, false>(sb, acc, g_x + (size_t)mt * 64 * DIMX, DIMX,
                              g_wv + nt * 128, DV, DIMX / 64);
#pragma unroll
        for (int i = 0; i < 2; i++)
#pragma unroll
            for (int rr = 0; rr < 2; rr++) {
                int row = mt * 64 + wm * 32 + i * 16 + t4 + 8 * rr;
#pragma unroll
                for (int j = 0; j < 4; j++) {
                    int c = nt * 128 + wn * 32 + j * 8 + 2 * tm4;
                    float f0 = silu_f(acc[i][j][2 * rr + 0] + bv[c]);
                    float f1 = silu_f(acc[i][j][2 * rr + 1] + bv[c + 1]);
                    *reinterpret_cast<uint32_t*>(g_v + (size_t)row * DV + c) = pack_h2(f0, f1);
                }
            }
    }
}

// causal tiles: rows it*64..+64, cols jt*128..+128, jt <= it/2. 272 tiles/batch.
// bias window staged in smem; full-tile fast path without predicates.
__global__ __launch_bounds__(256, 3) void tc_sim()
{
    extern __shared__ __align__(1024) char smem[];
    uint32_t sb = smem_to_u32(smem);
    float* s_bias = reinterpret_cast<float*>(smem + 2 * (8192 + 16384));
    int t = blockIdx.x;
    const int b = blockIdx.y;
    int it = 0, c0 = 0;
    while (c0 + (it >> 1) + 1 <= t) { c0 += (it >> 1) + 1; it++; }
    const int jt = t - c0;
    const int dmin = it * 64 - jt * 128 - 127;   // may be negative on diagonal tiles
    // stage bias window [dmin, dmin+191] (clamped) into smem
    if (threadIdx.x < 192) {
        int d = dmin + (int)threadIdx.x;
        d = d < 0 ? 0 : (d > SS - 1 ? SS - 1 : d);
        s_bias[threadIdx.x] = g_bias[d];
    }
    const size_t qoff = ((size_t)b * SS + it * 64) * DQK;
    const size_t koff = ((size_t)b * SS + jt * 128) * DQK;
    float acc[2][4][4];
    gemm_run<false, false>(sb, acc, g_q + qoff, DQK, g_k + koff, DQK, DQK / 64);
    const int tid = threadIdx.x, lane = tid & 31, wid = tid >> 5;
    const int wm = wid & 1, wn = wid >> 1, t4 = lane >> 2, tm4 = lane & 3;
    const float invS = 1.0f / (float)SS;
    __half* arow = g_attn + (size_t)b * SS * SS;
    const bool full = (jt * 128 + 127) <= (it * 64);  // fully unmasked tile
    const int li = wm * 32 + t4;                // local row base (i,rr add below)
    const int lj = wn * 32 + 2 * tm4;           // local col base
#pragma unroll
    for (int i = 0; i < 2; i++)
#pragma unroll
        for (int rr = 0; rr < 2; rr++) {
            const int lrow = li + i * 16 + 8 * rr;
            const int gi = it * 64 + lrow;
            // widx for j=0: (gi - gj0) - dmin, gj0 = jt*128 + lj
            const int w0 = (gi - (jt * 128 + lj)) - dmin;
            uint32_t obase = (uint32_t)gi * SS + (uint32_t)(jt * 128 + lj);
            if (full) {
#pragma unroll
                for (int j = 0; j < 4; j++) {
                    int wj = w0 - j * 8;
                    float v0 = lapl_f(acc[i][j][2 * rr + 0] * invS + s_bias[wj]);
                    float v1 = lapl_f(acc[i][j][2 * rr + 1] * invS + s_bias[wj - 1]);
                    *reinterpret_cast<uint32_t*>(arow + obase + j * 8) = pack_h2(v0, v1);
                }
            } else {
#pragma unroll
                for (int j = 0; j < 4; j++) {
                    int wj = w0 - j * 8;             // = gi - gj - dmin
                    float v0 = 0.0f, v1 = 0.0f;
                    if (wj + dmin >= 0)
                        v0 = lapl_f(acc[i][j][2 * rr + 0] * invS + s_bias[wj]);
                    if (wj - 1 + dmin >= 0)
                        v1 = lapl_f(acc[i][j][2 * rr + 1] * invS + s_bias[wj - 1]);
                    *reinterpret_cast<uint32_t*>(arow + obase + j * 8) = pack_h2(v0, v1);
                }
            }
        }
}

__global__ __launch_bounds__(256, 2) void tc_out(float* __restrict__ out)
{
    extern __shared__ __align__(1024) char smem[];
    uint32_t sb = smem_to_u32(smem);
    const int nt = blockIdx.x;
    const int it = 31 - blockIdx.y;   // heaviest first
    const int b = blockIdx.z;
    const int nk = it + 1;            // K extent = (it+1)*64
    const size_t aoff = ((size_t)b * SS + it * 64) * SS;
    float acc[2][4][4];
    gemm_run<true, true>(sb, acc, g_attn + aoff, SS,
                         g_v + (size_t)b * SS * DV + nt * 128, DV, nk);
    const int tid = threadIdx.x, lane = tid & 31, wid = tid >> 5;
    const int wm = wid & 1, wn = wid >> 1, t4 = lane >> 2, tm4 = lane & 3;
#pragma unroll
    for (int i = 0; i < 2; i++)
#pragma unroll
        for (int rr = 0; rr < 2; rr++) {
            int row = it * 64 + wm * 32 + i * 16 + t4 + 8 * rr;
#pragma unroll
            for (int j = 0; j < 4; j++) {
                int c = nt * 128 + wn * 32 + j * 8 + 2 * tm4;
                float2 v;
                v.x = acc[i][j][2 * rr + 0];
                v.y = acc[i][j][2 * rr + 1];
                *reinterpret_cast<float2*>(out + ((size_t)b * SS + row) * DV + c) = v;
            }
        }
}

// ---------------------------------------------------------------------------
// launch (single stream)
// ---------------------------------------------------------------------------
extern "C" void kernel_launch(void* const* d_in, const int* in_sizes, int n_in,
                              void* d_out, int out_size)
{
    const float* x     = (const float*)d_in[0];
    const float* wqk   = (const float*)d_in[1];
    const float* bqk   = (const float*)d_in[2];
    const float* gamma = (const float*)d_in[3];
    const float* beta  = (const float*)d_in[4];
    const float* wv    = (const float*)d_in[5];
    const float* bv    = (const float*)d_in[6];
    const float* rel   = (const float*)d_in[7];
    float* out = (float*)d_out;

    cudaFuncSetAttribute(tc_proj, cudaFuncAttributeMaxDynamicSharedMemorySize, SMEM_PROJ);
    cudaFuncSetAttribute(tc_sim,  cudaFuncAttributeMaxDynamicSharedMemorySize, SMEM_SIM);
    cudaFuncSetAttribute(tc_out,  cudaFuncAttributeMaxDynamicSharedMemorySize, SMEM_OUT);

    prep_kernel<<<PREP_BLOCKS, 256>>>(x, wqk, wv, rel);
    tc_proj<<<128 + 1024, 256, SMEM_PROJ>>>(bqk, gamma, beta, bv);
    tc_sim<<<dim3(272, BB), 256, SMEM_SIM>>>();
    tc_out<<<dim3(DV / 128, SS / 64, BB), 256, SMEM_OUT>>>(out);
}

// round 16
// speedup vs baseline: 1.0516x; 1.0142x over previous
#include <cuda_runtime.h>
#include <cuda_fp16.h>
#include <math.h>
#include <stdint.h>

#define BB 4
#define SS 2048
#define DIMX 1024
#define DQK 128
#define DV 1024
#define MROWS (BB * SS)   // 8192

// ---------------------------------------------------------------------------
// scratch (__device__ globals; no dynamic allocation)
// ---------------------------------------------------------------------------
__device__ __align__(256) __half g_x[(size_t)MROWS * DIMX];
__device__ __align__(256) __half g_wqk[DIMX * DQK];                // [k][n]
__device__ __align__(256) __half g_wv[(size_t)DIMX * DV];          // [k][n]
__device__ __align__(256) __half g_q[(size_t)MROWS * DQK];
__device__ __align__(256) __half g_k[(size_t)MROWS * DQK];
__device__ __align__(256) __half g_v[(size_t)MROWS * DV];          // [row][dv]
__device__ __align__(256) __half g_attn[(size_t)BB * SS * SS];
__device__ float g_bias[SS];

// ---------------------------------------------------------------------------
// PDL helpers
// ---------------------------------------------------------------------------
__device__ __forceinline__ void pdl_wait() {
    asm volatile("griddepcontrol.wait;" ::: "memory");
}
__device__ __forceinline__ void pdl_trigger() {
    asm volatile("griddepcontrol.launch_dependents;" ::: "memory");
}

// ---------------------------------------------------------------------------
// helpers
// ---------------------------------------------------------------------------
__device__ __forceinline__ uint32_t smem_to_u32(const void* p) {
    uint32_t a;
    asm("{ .reg .u64 t; cvta.to.shared.u64 t, %1; cvt.u32.u64 %0, t; }"
        : "=r"(a) : "l"(p));
    return a;
}
__device__ __forceinline__ uint32_t sw128(uint32_t o) {
    return o ^ ((o >> 3) & 0x70);
}
__device__ __forceinline__ void cp16(uint32_t dst, const void* src) {
    asm volatile("cp.async.cg.shared.global [%0], [%1], 16;" :: "r"(dst), "l"(src));
}
__device__ __forceinline__ void ldmx4(uint32_t* r, uint32_t a) {
    asm volatile("ldmatrix.sync.aligned.m8n8.x4.shared.b16 {%0,%1,%2,%3}, [%4];"
        : "=r"(r[0]), "=r"(r[1]), "=r"(r[2]), "=r"(r[3]) : "r"(a));
}
__device__ __forceinline__ void ldmx4t(uint32_t* r, uint32_t a) {
    asm volatile("ldmatrix.sync.aligned.m8n8.x4.trans.shared.b16 {%0,%1,%2,%3}, [%4];"
        : "=r"(r[0]), "=r"(r[1]), "=r"(r[2]), "=r"(r[3]) : "r"(a));
}
__device__ __forceinline__ void mma16816(float* d, const uint32_t* a, const uint32_t* b) {
    asm volatile(
        "mma.sync.aligned.m16n8k16.row.col.f32.f16.f16.f32 "
        "{%0,%1,%2,%3}, {%4,%5,%6,%7}, {%8,%9}, {%0,%1,%2,%3};"
        : "+f"(d[0]), "+f"(d[1]), "+f"(d[2]), "+f"(d[3])
        : "r"(a[0]), "r"(a[1]), "r"(a[2]), "r"(a[3]), "r"(b[0]), "r"(b[1]));
}

__device__ __forceinline__ float silu_f(float x) { return x / (1.0f + expf(-x)); }
__device__ __forceinline__ float lapl_f(float x) {
    return 0.5f * (1.0f + erff((x - 0.70710678118654746f) * 0.79788456080286541f));
}
__device__ __forceinline__ uint32_t pack_h2(float a, float b) {
    __half2 h2 = __floats2half2_rn(a, b);
    return *reinterpret_cast<uint32_t*>(&h2);
}

// ---------------------------------------------------------------------------
// tile geometry: CTA 64x128, chunk K=64, 256 threads, 8 warps (2m x 4n),
// warp tile 32x32. A tile: 64 rows x 128B SW128. B(nmajor): 128 rows x 128B
// SW128. B(kmajor/trans): 64 rows x 272B. 2-stage smem pipeline.
// DBUF: register double-buffered fragments (tc_out only).
// ---------------------------------------------------------------------------
#define ATILE 8192
template <int ROWS>
__device__ __forceinline__ void ld_tile_nmajor(uint32_t dst, const __half* src,
                                               int ld, int tid) {
#pragma unroll
    for (int s = 0; s < ROWS / 32; s++) {
        int idx = tid + s * 256;
        int row = idx >> 3, seg = idx & 7;
        uint32_t off = (uint32_t)(row * 128 + seg * 16);
        cp16(dst + sw128(off), src + (size_t)row * ld + seg * 8);
    }
}
__device__ __forceinline__ void ld_tile_kmajor(uint32_t dst, const __half* src,
                                               int ld, int tid) {
#pragma unroll
    for (int s = 0; s < 4; s++) {
        int idx = tid + s * 256;
        int row = idx >> 4, seg = idx & 15;
        cp16(dst + (uint32_t)(row * 272 + seg * 16), src + (size_t)row * ld + seg * 8);
    }
}

template <bool BTRANS>
__device__ __forceinline__ void ld_frags(uint32_t A_s, uint32_t B_s,
                                         const uint32_t* a_raw, const uint32_t* b_raw,
                                         int ks, uint32_t ah[2][4], uint32_t bh[2][4]) {
#pragma unroll
    for (int i = 0; i < 2; i++)
        ldmx4(ah[i], A_s + sw128(a_raw[i] + ks * 32));
    if (!BTRANS) {
#pragma unroll
        for (int g = 0; g < 2; g++)
            ldmx4(bh[g], B_s + sw128(b_raw[g] + ks * 32));
    } else {
#pragma unroll
        for (int g = 0; g < 2; g++)
            ldmx4t(bh[g], B_s + b_raw[g] + ks * 4352);
    }
}

template <bool BTRANS, bool DBUF>
__device__ __forceinline__ void compute_stage(uint32_t st, float acc[2][4][4], int tid) {
    const int lane = tid & 31, wid = tid >> 5, wm = wid & 1, wn = wid >> 1;
    uint32_t a_raw[2];
#pragma unroll
    for (int i = 0; i < 2; i++) {
        uint32_t row = wm * 32 + i * 16 + (lane & 15);
        a_raw[i] = row * 128 + ((lane >> 4) << 4);
    }
    uint32_t b_raw[2];
    const uint32_t m = lane >> 3;
    if (!BTRANS) {
#pragma unroll
        for (int g = 0; g < 2; g++) {
            uint32_t row = wn * 32 + g * 16 + ((m >> 1) << 3) + (lane & 7);
            b_raw[g] = row * 128 + ((m & 1) << 4);
        }
    } else {
#pragma unroll
        for (int g = 0; g < 2; g++) {
            uint32_t krow = ((m & 1) << 3) + (lane & 7);
            uint32_t ncol = wn * 32 + g * 16 + ((m >> 1) << 3);
            b_raw[g] = krow * 272 + ncol * 2;
        }
    }
    const uint32_t A_s = st, B_s = st + ATILE;

    if (DBUF) {
        uint32_t ah[2][2][4], bh[2][2][4];
        ld_frags<BTRANS>(A_s, B_s, a_raw, b_raw, 0, ah[0], bh[0]);
#pragma unroll
        for (int ks = 0; ks < 4; ks++) {
            const int cur = ks & 1, nxt = cur ^ 1;
            if (ks < 3)
                ld_frags<BTRANS>(A_s, B_s, a_raw, b_raw, ks + 1, ah[nxt], bh[nxt]);
#pragma unroll
            for (int i = 0; i < 2; i++)
#pragma unroll
                for (int j = 0; j < 4; j++)
                    mma16816(acc[i][j], ah[cur][i], &bh[cur][j >> 1][(j & 1) * 2]);
        }
    } else {
#pragma unroll
        for (int ks = 0; ks < 4; ks++) {
            uint32_t ah[2][4], bh[2][4];
            ld_frags<BTRANS>(A_s, B_s, a_raw, b_raw, ks, ah, bh);
#pragma unroll
            for (int i = 0; i < 2; i++)
#pragma unroll
                for (int j = 0; j < 4; j++)
                    mma16816(acc[i][j], ah[i], &bh[j >> 1][(j & 1) * 2]);
        }
    }
}

// 2-stage pipeline; single __syncthreads per chunk
template <bool BTRANS, bool DBUF>
__device__ __forceinline__ void gemm_run(uint32_t sb, float acc[2][4][4],
    const __half* A, int lda, const __half* B, int ldb, int nk)
{
    constexpr uint32_t BTILE = BTRANS ? 17408u : 16384u;
    constexpr uint32_t STAGE = ATILE + BTILE;
    const int tid = threadIdx.x;
#pragma unroll
    for (int i = 0; i < 2; i++)
#pragma unroll
        for (int j = 0; j < 4; j++)
#pragma unroll
            for (int r = 0; r < 4; r++) acc[i][j][r] = 0.0f;

#define LOAD_CHUNK(stg, c) do {                                                      \
        uint32_t base_ = sb + (stg) * STAGE;                                         \
        ld_tile_nmajor<64>(base_, A + (size_t)(c) * 64, lda, tid);                   \
        if (BTRANS) ld_tile_kmajor(base_ + ATILE, B + (size_t)(c) * 64 * ldb, ldb, tid); \
        else        ld_tile_nmajor<128>(base_ + ATILE, B + (size_t)(c) * 64, ldb, tid); \
    } while (0)

    LOAD_CHUNK(0, 0);
    asm volatile("cp.async.commit_group;");
    for (int i = 0; i < nk; i++) {
        int st = i & 1;
        asm volatile("cp.async.wait_group 0;");
        __syncthreads();
        if (i + 1 < nk) {
            LOAD_CHUNK(st ^ 1, i + 1);
            asm volatile("cp.async.commit_group;");
        }
        compute_stage<BTRANS, DBUF>(sb + st * STAGE, acc, tid);
    }
#undef LOAD_CHUNK
}

#define SMEM_PROJ (2 * (8192 + 17408))          // 51200
#define SMEM_SIM  (2 * (8192 + 16384) + 1024)   // 50176 (+bias window)
#define SMEM_OUT  (2 * (8192 + 17408))          // 51200

// ---------------------------------------------------------------------------
// prep: converts x, wqk, wv (4 independent vec4 per thread) + bias table
// ---------------------------------------------------------------------------
#define NX ((size_t)MROWS * DIMX)                 // 8388608
#define NWQ ((size_t)DIMX * DQK)                  // 131072
#define NWV ((size_t)DIMX * DV)                   // 1048576
#define CVT_TOTAL ((NX + NWQ + NWV) / 4)          // 2392064 vec4 elements
#define PREP_THREADS ((CVT_TOTAL + 3) / 4)        // 598016
#define PREP_BLOCKS ((PREP_THREADS + 255) / 256)  // 2336

__device__ __forceinline__ void cvt_one(const float* __restrict__ x,
                                        const float* __restrict__ wqk,
                                        const float* __restrict__ wv, size_t vi) {
    const float* src;
    __half* dst;
    size_t off;
    if (vi < NX / 4) {
        src = x; dst = g_x; off = vi * 4;
    } else if (vi < (NX + NWQ) / 4) {
        src = wqk; dst = g_wqk; off = vi * 4 - NX;
    } else {
        src = wv; dst = g_wv; off = vi * 4 - NX - NWQ;
    }
    float4 f = *reinterpret_cast<const float4*>(src + off);
    uint2 o;
    o.x = pack_h2(f.x, f.y);
    o.y = pack_h2(f.z, f.w);
    *reinterpret_cast<uint2*>(dst + off) = o;
}

__global__ void prep_kernel(const float* __restrict__ x, const float* __restrict__ wqk,
                            const float* __restrict__ wv, const float* __restrict__ table) {
    size_t t = (size_t)blockIdx.x * blockDim.x + threadIdx.x;
    if (t < SS) {
        int d = (int)t;
        int bkt;
        if (d < 16) {
            bkt = d;
        } else {
            float tt = logf((float)d * 0.0625f) * (16.0f / 2.0794415416798357f);
            int v = 16 + (int)tt;
            bkt = v < 31 ? v : 31;
        }
        g_bias[d] = table[bkt] * 11.313708498984761f;
    }
#pragma unroll
    for (int s = 0; s < 4; s++) {
        size_t vi = t + (size_t)s * PREP_THREADS;
        if (vi < CVT_TOTAL) cvt_one(x, wqk, wv, vi);
    }
    pdl_trigger();
}

// ---------------------------------------------------------------------------
// GEMM kernels (CTA tile 64x128); merged projections
// ---------------------------------------------------------------------------
__global__ __launch_bounds__(256, 3) void tc_proj(
    const float* __restrict__ bqk, const float* __restrict__ gamma,
    const float* __restrict__ beta, const float* __restrict__ bv)
{
    extern __shared__ __align__(1024) char smem[];
    uint32_t sb = smem_to_u32(smem);
    const int tid = threadIdx.x, lane = tid & 31, wid = tid >> 5;
    const int wm = wid & 1, wn = wid >> 1, t4 = lane >> 2, tm4 = lane & 3;
    float acc[2][4][4];
    pdl_wait();

    if (blockIdx.x < 128) {
        const int mt = blockIdx.x;
        gemm_run<true, false>(sb, acc, g_x + (size_t)mt * 64 * DIMX, DIMX,
                              g_wqk, DQK, DIMX / 64);
#pragma unroll
        for (int i = 0; i < 2; i++)
#pragma unroll
            for (int rr = 0; rr < 2; rr++) {
                int row = mt * 64 + wm * 32 + i * 16 + t4 + 8 * rr;
#pragma unroll
                for (int j = 0; j < 4; j++) {
                    int c = wn * 32 + j * 8 + 2 * tm4;
                    float f0 = silu_f(acc[i][j][2 * rr + 0] + bqk[c]);
                    float f1 = silu_f(acc[i][j][2 * rr + 1] + bqk[c + 1]);
                    float q0 = f0 * gamma[c] + beta[c];
                    float q1 = f1 * gamma[c + 1] + beta[c + 1];
                    float k0 = f0 * gamma[DQK + c] + beta[DQK + c];
                    float k1 = f1 * gamma[DQK + c + 1] + beta[DQK + c + 1];
                    size_t o = (size_t)row * DQK + c;
                    *reinterpret_cast<uint32_t*>(g_q + o) = pack_h2(q0, q1);
                    *reinterpret_cast<uint32_t*>(g_k + o) = pack_h2(k0, k1);
                }
            }
    } else {
        const int id = blockIdx.x - 128;
        const int nt = id & 7, mt = id >> 3;
        gemm_run<true, false>(sb, acc, g_x + (size_t)mt * 64 * DIMX, DIMX,
                              g_wv + nt * 128, DV, DIMX / 64);
#pragma unroll
        for (int i = 0; i < 2; i++)
#pragma unroll
            for (int rr = 0; rr < 2; rr++) {
                int row = mt * 64 + wm * 32 + i * 16 + t4 + 8 * rr;
#pragma unroll
                for (int j = 0; j < 4; j++) {
                    int c = nt * 128 + wn * 32 + j * 8 + 2 * tm4;
                    float f0 = silu_f(acc[i][j][2 * rr + 0] + bv[c]);
                    float f1 = silu_f(acc[i][j][2 * rr + 1] + bv[c + 1]);
                    *reinterpret_cast<uint32_t*>(g_v + (size_t)row * DV + c) = pack_h2(f0, f1);
                }
            }
    }
    pdl_trigger();
}

// causal tiles: rows it*64..+64, cols jt*128..+128, jt <= it/2. 272 tiles/batch.
__global__ __launch_bounds__(256, 3) void tc_sim()
{
    extern __shared__ __align__(1024) char smem[];
    uint32_t sb = smem_to_u32(smem);
    float* s_bias = reinterpret_cast<float*>(smem + 2 * (8192 + 16384));
    int t = blockIdx.x;
    const int b = blockIdx.y;
    int it = 0, c0 = 0;
    while (c0 + (it >> 1) + 1 <= t) { c0 += (it >> 1) + 1; it++; }
    const int jt = t - c0;
    const int dmin = it * 64 - jt * 128 - 127;
    pdl_wait();
    if (threadIdx.x < 192) {
        int d = dmin + (int)threadIdx.x;
        d = d < 0 ? 0 : (d > SS - 1 ? SS - 1 : d);
        s_bias[threadIdx.x] = g_bias[d];
    }
    const size_t qoff = ((size_t)b * SS + it * 64) * DQK;
    const size_t koff = ((size_t)b * SS + jt * 128) * DQK;
    float acc[2][4][4];
    gemm_run<false, false>(sb, acc, g_q + qoff, DQK, g_k + koff, DQK, DQK / 64);
    const int tid = threadIdx.x, lane = tid & 31, wid = tid >> 5;
    const int wm = wid & 1, wn = wid >> 1, t4 = lane >> 2, tm4 = lane & 3;
    const float invS = 1.0f / (float)SS;
    __half* arow = g_attn + (size_t)b * SS * SS;
    const bool full = (jt * 128 + 127) <= (it * 64);
    const int li = wm * 32 + t4;
    const int lj = wn * 32 + 2 * tm4;
#pragma unroll
    for (int i = 0; i < 2; i++)
#pragma unroll
        for (int rr = 0; rr < 2; rr++) {
            const int lrow = li + i * 16 + 8 * rr;
            const int gi = it * 64 + lrow;
            const int w0 = (gi - (jt * 128 + lj)) - dmin;
            uint32_t obase = (uint32_t)gi * SS + (uint32_t)(jt * 128 + lj);
            if (full) {
#pragma unroll
                for (int j = 0; j < 4; j++) {
                    int wj = w0 - j * 8;
                    float v0 = lapl_f(acc[i][j][2 * rr + 0] * invS + s_bias[wj]);
                    float v1 = lapl_f(acc[i][j][2 * rr + 1] * invS + s_bias[wj - 1]);
                    *reinterpret_cast<uint32_t*>(arow + obase + j * 8) = pack_h2(v0, v1);
                }
            } else {
#pragma unroll
                for (int j = 0; j < 4; j++) {
                    int wj = w0 - j * 8;
                    float v0 = 0.0f, v1 = 0.0f;
                    if (wj + dmin >= 0)
                        v0 = lapl_f(acc[i][j][2 * rr + 0] * invS + s_bias[wj]);
                    if (wj - 1 + dmin >= 0)
                        v1 = lapl_f(acc[i][j][2 * rr + 1] * invS + s_bias[wj - 1]);
                    *reinterpret_cast<uint32_t*>(arow + obase + j * 8) = pack_h2(v0, v1);
                }
            }
        }
    pdl_trigger();
}

__global__ __launch_bounds__(256, 2) void tc_out(float* __restrict__ out)
{
    extern __shared__ __align__(1024) char smem[];
    uint32_t sb = smem_to_u32(smem);
    const int nt = blockIdx.x;
    const int it = 31 - blockIdx.y;   // heaviest first
    const int b = blockIdx.z;
    const int nk = it + 1;            // K extent = (it+1)*64
    const size_t aoff = ((size_t)b * SS + it * 64) * SS;
    float acc[2][4][4];
    pdl_wait();
    gemm_run<true, true>(sb, acc, g_attn + aoff, SS,
                         g_v + (size_t)b * SS * DV + nt * 128, DV, nk);
    const int tid = threadIdx.x, lane = tid & 31, wid = tid >> 5;
    const int wm = wid & 1, wn = wid >> 1, t4 = lane >> 2, tm4 = lane & 3;
#pragma unroll
    for (int i = 0; i < 2; i++)
#pragma unroll
        for (int rr = 0; rr < 2; rr++) {
            int row = it * 64 + wm * 32 + i * 16 + t4 + 8 * rr;
#pragma unroll
            for (int j = 0; j < 4; j++) {
                int c = nt * 128 + wn * 32 + j * 8 + 2 * tm4;
                float2 v;
                v.x = acc[i][j][2 * rr + 0];
                v.y = acc[i][j][2 * rr + 1];
                *reinterpret_cast<float2*>(out + ((size_t)b * SS + row) * DV + c) = v;
            }
        }
}

// ---------------------------------------------------------------------------
// launch: single stream; PDL chains prep -> proj -> sim -> out
// ---------------------------------------------------------------------------
template <typename... Args>
static void launch_pdl(void (*kern)(Args...), dim3 grid, dim3 block,
                       size_t smem, Args... args)
{
    cudaLaunchConfig_t cfg = {};
    cfg.gridDim = grid;
    cfg.blockDim = block;
    cfg.dynamicSmemBytes = smem;
    cfg.stream = 0;
    cudaLaunchAttribute attr[1];
    attr[0].id = cudaLaunchAttributeProgrammaticStreamSerialization;
    attr[0].val.programmaticStreamSerializationAllowed = 1;
    cfg.attrs = attr;
    cfg.numAttrs = 1;
    cudaLaunchKernelEx(&cfg, kern, args...);
}

extern "C" void kernel_launch(void* const* d_in, const int* in_sizes, int n_in,
                              void* d_out, int out_size)
{
    const float* x     = (const float*)d_in[0];
    const float* wqk   = (const float*)d_in[1];
    const float* bqk   = (const float*)d_in[2];
    const float* gamma = (const float*)d_in[3];
    const float* beta  = (const float*)d_in[4];
    const float* wv    = (const float*)d_in[5];
    const float* bv    = (const float*)d_in[6];
    const float* rel   = (const float*)d_in[7];
    float* out = (float*)d_out;

    cudaFuncSetAttribute(tc_proj, cudaFuncAttributeMaxDynamicSharedMemorySize, SMEM_PROJ);
    cudaFuncSetAttribute(tc_sim,  cudaFuncAttributeMaxDynamicSharedMemorySize, SMEM_SIM);
    cudaFuncSetAttribute(tc_out,  cudaFuncAttributeMaxDynamicSharedMemorySize, SMEM_OUT);

    prep_kernel<<<PREP_BLOCKS, 256>>>(x, wqk, wv, rel);
    launch_pdl(tc_proj, dim3(128 + 1024), dim3(256), (size_t)SMEM_PROJ,
               bqk, gamma, beta, bv);
    launch_pdl(tc_sim, dim3(272, BB), dim3(256), (size_t)SMEM_SIM);
    launch_pdl(tc_out, dim3(DV / 128, SS / 64, BB), dim3(256), (size_t)SMEM_OUT, out);
}